// round 9
// baseline (speedup 1.0000x reference)
#include <cuda_runtime.h>
#include <cuda_fp16.h>
#include <cstdint>

// Problem constants (fixed by the dataset)
#define KBITS 8
#define MDIM  1024   // in_features  (GEMM K)
#define NDIM  1024   // out_features
#define TROWS 8192   // B*S

// ---------------------------------------------------------------------------
// Device scratch: only the folded weight now (x converted in-GEMM)
// ---------------------------------------------------------------------------
__device__ __half g_w[NDIM * MDIM];     // 2 MB  W^T fp16 [n][m] (k-contig)

__device__ __forceinline__ uint32_t smem_u32(const void* p) {
    uint32_t a;
    asm("{ .reg .u64 t; cvta.to.shared.u64 t, %1; cvt.u32.u64 %0, t; }" : "=r"(a) : "l"(p));
    return a;
}

// ---------------------------------------------------------------------------
// Prep: fold binary*scale -> W, transpose to [n][m], cast fp16.
// Block covers 128 n x 32 m. float4 across n for 4x MLP.
// ---------------------------------------------------------------------------
__global__ __launch_bounds__(256)
void fold_kernel(const float* __restrict__ binary,
                 const float* __restrict__ scale) {
    __shared__ float tile[32][132];     // [m][n], +4 pad
    const int n0 = blockIdx.x * 128;
    const int m0 = blockIdx.y * 32;
    const int t = threadIdx.x;
    const int nc = (t & 31) * 4;        // n offset within 128
    const int mr = t >> 5;              // 0..7

    float4 s[KBITS];
#pragma unroll
    for (int k = 0; k < KBITS; k++)
        s[k] = *reinterpret_cast<const float4*>(scale + k * NDIM + n0 + nc);

#pragma unroll
    for (int r = 0; r < 4; r++) {
        int m = m0 + mr + r * 8;
        float4 acc = make_float4(0.f, 0.f, 0.f, 0.f);
#pragma unroll
        for (int k = 0; k < KBITS; k++) {
            float4 b = *reinterpret_cast<const float4*>(
                binary + (size_t)k * MDIM * NDIM + (size_t)m * NDIM + n0 + nc);
            acc.x += b.x * s[k].x;
            acc.y += b.y * s[k].y;
            acc.z += b.z * s[k].z;
            acc.w += b.w * s[k].w;
        }
        *reinterpret_cast<float4*>(&tile[mr + r * 8][nc]) = acc;
    }
    __syncthreads();

    // transpose out: 128 n-rows, 2 threads per row, 16 halves (32 B) each
    const int n = t >> 1;
    const int mh = (t & 1) * 16;
    __half h[16];
#pragma unroll
    for (int i = 0; i < 16; i++)
        h[i] = __float2half_rn(tile[mh + i][n]);
    size_t dst = (size_t)(n0 + n) * MDIM + m0 + mh;
    *reinterpret_cast<uint4*>(g_w + dst)     = reinterpret_cast<uint4*>(h)[0];
    *reinterpret_cast<uint4*>(g_w + dst + 8) = reinterpret_cast<uint4*>(h)[1];
}

// ---------------------------------------------------------------------------
// GEMM: out = fp16(x) @ W + bias  via mma.sync fp16 (fp32 accum)
// A (x) loaded as fp32 LDG -> cvt -> STS (fused conversion, no prep kernel).
// B (W) via cp.async. CTA 128x128, 8 warps (64x32 warp tiles), KC=64,
// 3-stage smem ring, occ 2.
// ---------------------------------------------------------------------------
#define BM 128
#define BN 128
#define KC 64
#define STAGES 3
#define TILE_B   (128 * 128)           // one fp16 operand tile: 16 KB
#define STAGE_B  (2 * TILE_B)          // A + B = 32 KB
#define SMEM_DYN (STAGES * STAGE_B + 128)

__device__ __forceinline__ void cp16(uint32_t saddr, const void* gaddr) {
    asm volatile("cp.async.cg.shared.global [%0], [%1], 16;"
                 :: "r"(saddr), "l"(gaddr) : "memory");
}
__device__ __forceinline__ void ldsm_x4(uint32_t* r, uint32_t addr) {
    asm volatile("ldmatrix.sync.aligned.m8n8.x4.shared.b16 {%0,%1,%2,%3}, [%4];"
                 : "=r"(r[0]), "=r"(r[1]), "=r"(r[2]), "=r"(r[3]) : "r"(addr));
}
__device__ __forceinline__ void mma_f16(float* d, const uint32_t* a, const uint32_t* b) {
    asm volatile("mma.sync.aligned.m16n8k16.row.col.f32.f16.f16.f32 "
                 "{%0,%1,%2,%3}, {%4,%5,%6,%7}, {%8,%9}, {%0,%1,%2,%3};"
                 : "+f"(d[0]), "+f"(d[1]), "+f"(d[2]), "+f"(d[3])
                 : "r"(a[0]), "r"(a[1]), "r"(a[2]), "r"(a[3]), "r"(b[0]), "r"(b[1]));
}
// store 8 halves (from 2 float4) to smem
__device__ __forceinline__ void sts_cvt8(uint32_t saddr, float4 v0, float4 v1) {
    __half2 h0 = __float22half2_rn(make_float2(v0.x, v0.y));
    __half2 h1 = __float22half2_rn(make_float2(v0.z, v0.w));
    __half2 h2 = __float22half2_rn(make_float2(v1.x, v1.y));
    __half2 h3 = __float22half2_rn(make_float2(v1.z, v1.w));
    asm volatile("st.shared.v4.b32 [%0], {%1,%2,%3,%4};"
                 :: "r"(saddr),
                    "r"(*reinterpret_cast<uint32_t*>(&h0)),
                    "r"(*reinterpret_cast<uint32_t*>(&h1)),
                    "r"(*reinterpret_cast<uint32_t*>(&h2)),
                    "r"(*reinterpret_cast<uint32_t*>(&h3)) : "memory");
}

__global__ __launch_bounds__(256, 2)
void gemm_kernel(const float* __restrict__ x,
                 const float* __restrict__ bias, float* __restrict__ out) {
    extern __shared__ char smem_raw[];
    const uint32_t sbase = (smem_u32(smem_raw) + 127u) & ~127u;

    const int tid = threadIdx.x;
    const int wid = tid >> 5, lid = tid & 31;
    const int warp_m = wid & 1;    // 2 warps along M (64 each)
    const int warp_n = wid >> 1;   // 4 warps along N (32 each)
    const int bx = blockIdx.x, by = blockIdx.y;

    const float* gAf = x + (size_t)by * BM * MDIM;           // fp32 A rows
    const char*  gB  = (const char*)(g_w + (size_t)bx * BN * MDIM);

    // A fused-load mapping: 1024 fp16 16B-chunks per tile, 4 per thread.
    // chunk <- 32 B of fp32 from x.
    int a_row[4], a_c[4];
    uint32_t a_dst[4];
#pragma unroll
    for (int i = 0; i < 4; i++) {
        int id = tid + i * 256;
        a_row[i] = id >> 3;
        a_c[i] = id & 7;
        a_dst[i] = a_row[i] * 128 + ((a_c[i] ^ (a_row[i] & 7)) << 4);
    }

    // ldmatrix row bases
    int arow[4];
#pragma unroll
    for (int f = 0; f < 4; f++) arow[f] = warp_m * 64 + f * 16 + (lid & 15);
    const int a_hl = lid >> 4;
    int brow[2];
#pragma unroll
    for (int u = 0; u < 2; u++)
        brow[u] = warp_n * 32 + u * 16 + ((lid >> 4) & 1) * 8 + (lid & 7);
    const int b_ch = (lid >> 3) & 1;

    float acc[4][4][4];
#pragma unroll
    for (int i = 0; i < 4; i++)
#pragma unroll
        for (int j = 0; j < 4; j++)
#pragma unroll
            for (int q = 0; q < 4; q++) acc[i][j][q] = 0.f;

    const int NCH = MDIM / KC;  // 16

    auto load_a = [&](int stage, int k0) {
        uint32_t sb = sbase + stage * STAGE_B;
#pragma unroll
        for (int i = 0; i < 4; i++) {
            const float* src = gAf + (size_t)a_row[i] * MDIM + k0 + a_c[i] * 8;
            float4 v0 = *reinterpret_cast<const float4*>(src);
            float4 v1 = *reinterpret_cast<const float4*>(src + 4);
            sts_cvt8(sb + a_dst[i], v0, v1);
        }
    };
    auto load_b = [&](int stage, int k0) {
        uint32_t sb = sbase + stage * STAGE_B + TILE_B;
#pragma unroll
        for (int i = 0; i < 4; i++) {
            size_t src = (size_t)a_row[i] * (MDIM * 2) + k0 * 2 + a_c[i] * 16;
            cp16(sb + a_dst[i], gB + src);
        }
        asm volatile("cp.async.commit_group;" ::: "memory");
    };

    // prologue: fill stages 0,1
    load_b(0, 0);
    load_b(1, KC);
    load_a(0, 0);
    load_a(1, KC);

    for (int c = 0; c < NCH; c++) {
        if (c + 2 < NCH)
            asm volatile("cp.async.wait_group 1;" ::: "memory");
        else
            asm volatile("cp.async.wait_group 0;" ::: "memory");
        __syncthreads();
        if (c + 2 < NCH) {
            load_b((c + 2) % STAGES, (c + 2) * KC);
            load_a((c + 2) % STAGES, (c + 2) * KC);
        }

        const uint32_t sA = sbase + (c % STAGES) * STAGE_B;
        const uint32_t sB = sA + TILE_B;
#pragma unroll
        for (int ks = 0; ks < 4; ks++) {
            uint32_t a[4][4], b[2][4];
#pragma unroll
            for (int f = 0; f < 4; f++)
                ldsm_x4(a[f], sA + arow[f] * 128 +
                              (((ks * 2 + a_hl) ^ (arow[f] & 7)) << 4));
#pragma unroll
            for (int u = 0; u < 2; u++)
                ldsm_x4(b[u], sB + brow[u] * 128 +
                              (((ks * 2 + b_ch) ^ (brow[u] & 7)) << 4));
#pragma unroll
            for (int i = 0; i < 4; i++)
#pragma unroll
                for (int j = 0; j < 4; j++)
                    mma_f16(acc[i][j], a[i], &b[j >> 1][(j & 1) * 2]);
        }
    }

    // ---- epilogue: bias + store ----
    const int row0 = by * BM + warp_m * 64;
    const int col0 = bx * BN + warp_n * 32;
    const int lrow = lid >> 2;
    const int lcol = (lid & 3) * 2;
#pragma unroll
    for (int j = 0; j < 4; j++) {
        int c0 = col0 + j * 8 + lcol;
        float2 bv = *reinterpret_cast<const float2*>(bias + c0);
#pragma unroll
        for (int i = 0; i < 4; i++) {
            int r = row0 + i * 16 + lrow;
            float2 o0 = {acc[i][j][0] + bv.x, acc[i][j][1] + bv.y};
            float2 o1 = {acc[i][j][2] + bv.x, acc[i][j][3] + bv.y};
            *reinterpret_cast<float2*>(out + (size_t)r * NDIM + c0) = o0;
            *reinterpret_cast<float2*>(out + (size_t)(r + 8) * NDIM + c0) = o1;
        }
    }
}

// ---------------------------------------------------------------------------
// Launch: fold, then GEMM (single stream; x converted inside the GEMM).
// ---------------------------------------------------------------------------
extern "C" void kernel_launch(void* const* d_in, const int* in_sizes, int n_in,
                              void* d_out, int out_size) {
    const float* x      = (const float*)d_in[0];  // [4,2048,1024]
    const float* binary = (const float*)d_in[1];  // [8,1024,1024]
    const float* scale  = (const float*)d_in[2];  // [8,1,1024]
    const float* bias   = (const float*)d_in[3];  // [1024]
    float* out = (float*)d_out;

    static int init = 0;
    if (!init) {
        cudaFuncSetAttribute(gemm_kernel, cudaFuncAttributeMaxDynamicSharedMemorySize, SMEM_DYN);
        init = 1;
    }

    fold_kernel<<<dim3(NDIM / 128, MDIM / 32), 256>>>(binary, scale);
    gemm_kernel<<<dim3(NDIM / BN, TROWS / BM), 256, SMEM_DYN>>>(x, bias, out);
}

// round 10
// speedup vs baseline: 1.3020x; 1.3020x over previous
#include <cuda_runtime.h>
#include <cuda_fp16.h>
#include <cstdint>

// Problem constants (fixed by the dataset)
#define KBITS 8
#define MDIM  1024   // in_features  (GEMM K)
#define NDIM  1024   // out_features
#define TROWS 8192   // B*S

// ---------------------------------------------------------------------------
// Device scratch
// ---------------------------------------------------------------------------
__device__ __half g_xh[TROWS * MDIM];   // 16 MB  fp16(x)
__device__ __half g_w[NDIM * MDIM];     //  2 MB  W^T fp16 [n][m] (k-contig)

__device__ __forceinline__ uint32_t smem_u32(const void* p) {
    uint32_t a;
    asm("{ .reg .u64 t; cvta.to.shared.u64 t, %1; cvt.u32.u64 %0, t; }" : "=r"(a) : "l"(p));
    return a;
}

// ---------------------------------------------------------------------------
// Prep 1: x -> fp16 (16 floats per thread)
// ---------------------------------------------------------------------------
__global__ __launch_bounds__(256)
void split_x_kernel(const float* __restrict__ x) {
    int idx = (blockIdx.x * 256 + threadIdx.x) * 16;
#pragma unroll
    for (int half = 0; half < 2; half++) {
        int o = idx + half * 8;
        float4 v0 = *reinterpret_cast<const float4*>(x + o);
        float4 v1 = *reinterpret_cast<const float4*>(x + o + 4);
        __half h[8];
        h[0] = __float2half_rn(v0.x); h[1] = __float2half_rn(v0.y);
        h[2] = __float2half_rn(v0.z); h[3] = __float2half_rn(v0.w);
        h[4] = __float2half_rn(v1.x); h[5] = __float2half_rn(v1.y);
        h[6] = __float2half_rn(v1.z); h[7] = __float2half_rn(v1.w);
        *reinterpret_cast<uint4*>(g_xh + o) = *reinterpret_cast<uint4*>(h);
    }
}

// ---------------------------------------------------------------------------
// Prep 2: fold binary*scale -> W, transpose to [n][m], cast fp16.
// Block covers 128 n x 32 m; float4 across n for 4x MLP. (verified in R9)
// ---------------------------------------------------------------------------
__global__ __launch_bounds__(256)
void fold_kernel(const float* __restrict__ binary,
                 const float* __restrict__ scale) {
    __shared__ float tile[32][132];     // [m][n], +4 pad
    const int n0 = blockIdx.x * 128;
    const int m0 = blockIdx.y * 32;
    const int t = threadIdx.x;
    const int nc = (t & 31) * 4;
    const int mr = t >> 5;

    float4 s[KBITS];
#pragma unroll
    for (int k = 0; k < KBITS; k++)
        s[k] = *reinterpret_cast<const float4*>(scale + k * NDIM + n0 + nc);

#pragma unroll
    for (int r = 0; r < 4; r++) {
        int m = m0 + mr + r * 8;
        float4 acc = make_float4(0.f, 0.f, 0.f, 0.f);
#pragma unroll
        for (int k = 0; k < KBITS; k++) {
            float4 b = *reinterpret_cast<const float4*>(
                binary + (size_t)k * MDIM * NDIM + (size_t)m * NDIM + n0 + nc);
            acc.x += b.x * s[k].x;
            acc.y += b.y * s[k].y;
            acc.z += b.z * s[k].z;
            acc.w += b.w * s[k].w;
        }
        *reinterpret_cast<float4*>(&tile[mr + r * 8][nc]) = acc;
    }
    __syncthreads();

    const int n = t >> 1;
    const int mh = (t & 1) * 16;
    __half h[16];
#pragma unroll
    for (int i = 0; i < 16; i++)
        h[i] = __float2half_rn(tile[mh + i][n]);
    size_t dst = (size_t)(n0 + n) * MDIM + m0 + mh;
    *reinterpret_cast<uint4*>(g_w + dst)     = reinterpret_cast<uint4*>(h)[0];
    *reinterpret_cast<uint4*>(g_w + dst + 8) = reinterpret_cast<uint4*>(h)[1];
}

// ---------------------------------------------------------------------------
// GEMM: out = xh @ W + bias  via mma.sync fp16 (fp32 accum)
// CTA 128x128, 4 warps (2x2 grid of 64x64 warp tiles), 128 threads,
// KC=32, 6-stage cp.async pipeline (prefetch distance 4), 2 CTAs/SM.
// SMEM rows 64 B (32 fp16); swizzle: chunk ^= ((row>>1)&3).
// ---------------------------------------------------------------------------
#define BM 128
#define BN 128
#define KC 32
#define STAGES 6
#define TILE_B   (128 * 64)            // one operand tile: 8 KB
#define STAGE_B  (2 * TILE_B)          // A + B = 16 KB
#define SMEM_DYN (STAGES * STAGE_B + 128)   // ~96 KB

__device__ __forceinline__ void cp16(uint32_t saddr, const void* gaddr) {
    asm volatile("cp.async.cg.shared.global [%0], [%1], 16;"
                 :: "r"(saddr), "l"(gaddr) : "memory");
}
__device__ __forceinline__ void cp_commit() {
    asm volatile("cp.async.commit_group;" ::: "memory");
}
__device__ __forceinline__ void ldsm_x4(uint32_t* r, uint32_t addr) {
    asm volatile("ldmatrix.sync.aligned.m8n8.x4.shared.b16 {%0,%1,%2,%3}, [%4];"
                 : "=r"(r[0]), "=r"(r[1]), "=r"(r[2]), "=r"(r[3]) : "r"(addr));
}
__device__ __forceinline__ void mma_f16(float* d, const uint32_t* a, const uint32_t* b) {
    asm volatile("mma.sync.aligned.m16n8k16.row.col.f32.f16.f16.f32 "
                 "{%0,%1,%2,%3}, {%4,%5,%6,%7}, {%8,%9}, {%0,%1,%2,%3};"
                 : "+f"(d[0]), "+f"(d[1]), "+f"(d[2]), "+f"(d[3])
                 : "r"(a[0]), "r"(a[1]), "r"(a[2]), "r"(a[3]), "r"(b[0]), "r"(b[1]));
}

__global__ __launch_bounds__(128, 2)
void gemm_kernel(const float* __restrict__ bias, float* __restrict__ out) {
    extern __shared__ char smem_raw[];
    const uint32_t sbase = (smem_u32(smem_raw) + 127u) & ~127u;

    const int tid = threadIdx.x;
    const int wid = tid >> 5, lid = tid & 31;
    const int warp_m = wid & 1;    // 2 warps along M (64 each)
    const int warp_n = wid >> 1;   // 2 warps along N (64 each)
    const int bx = blockIdx.x, by = blockIdx.y;

    const char* gA = (const char*)(g_xh + (size_t)by * BM * MDIM);
    const char* gB = (const char*)(g_w  + (size_t)bx * BN * MDIM);

    // cp.async mapping: 1024 16B-chunks per stage (512 A + 512 B), 8/thread.
    int ld_part[8], ld_row[8], ld_c[8];
    uint32_t ld_dst[8];
#pragma unroll
    for (int i = 0; i < 8; i++) {
        int id = tid + i * 128;
        ld_part[i] = id >> 9;            // 0 = A, 1 = B
        int rid = id & 511;
        ld_row[i] = rid >> 2;
        ld_c[i] = rid & 3;
        ld_dst[i] = ld_part[i] * TILE_B + ld_row[i] * 64 +
                    ((ld_c[i] ^ ((ld_row[i] >> 1) & 3)) << 4);
    }

    // ldmatrix offsets (ks=0); XOR 0x20 advances to ks=1
    uint32_t aoff[4];
#pragma unroll
    for (int f = 0; f < 4; f++) {
        int row = warp_m * 64 + f * 16 + (lid & 15);
        int hl = lid >> 4;
        aoff[f] = row * 64 + ((hl ^ ((row >> 1) & 3)) << 4);
    }
    uint32_t boff[4];
#pragma unroll
    for (int u = 0; u < 4; u++) {
        int nrow = warp_n * 64 + u * 16 + ((lid >> 4) & 1) * 8 + (lid & 7);
        int ch = (lid >> 3) & 1;
        boff[u] = nrow * 64 + ((ch ^ ((nrow >> 1) & 3)) << 4);
    }

    float acc[4][8][4];
#pragma unroll
    for (int i = 0; i < 4; i++)
#pragma unroll
        for (int j = 0; j < 8; j++)
#pragma unroll
            for (int q = 0; q < 4; q++) acc[i][j][q] = 0.f;

    const int NCH = MDIM / KC;  // 32
    auto issue = [&](int stage, int k0) {
        uint32_t sb = sbase + stage * STAGE_B;
#pragma unroll
        for (int i = 0; i < 8; i++) {
            const char* base = ld_part[i] ? gB : gA;
            cp16(sb + ld_dst[i],
                 base + (size_t)ld_row[i] * (MDIM * 2) + k0 * 2 + ld_c[i] * 16);
        }
        cp_commit();
    };

    // prologue: chunks 0..3 in flight
    issue(0, 0);
    issue(1, KC);
    issue(2, 2 * KC);
    issue(3, 3 * KC);

    for (int c = 0; c < NCH; c++) {
        // issue chunk c+4 into stage (c+4)%6 == (c-2)%6 (freed 2 chunks ago;
        // the sync in iteration c-1 ordered all its readers before us)
        if (c + 4 < NCH) issue((c + 4) % STAGES, (c + 4) * KC);
        else cp_commit();   // empty group keeps pending count uniform
        asm volatile("cp.async.wait_group 4;" ::: "memory");
        __syncthreads();

        const uint32_t sA = sbase + (c % STAGES) * STAGE_B;
        const uint32_t sB = sA + TILE_B;
#pragma unroll
        for (int ks = 0; ks < 2; ks++) {
            const uint32_t kx = ks << 5;
            uint32_t a[4][4], b[4][4];
#pragma unroll
            for (int f = 0; f < 4; f++) ldsm_x4(a[f], sA + (aoff[f] ^ kx));
#pragma unroll
            for (int u = 0; u < 4; u++) ldsm_x4(b[u], sB + (boff[u] ^ kx));
#pragma unroll
            for (int i = 0; i < 4; i++)
#pragma unroll
                for (int j = 0; j < 8; j++)
                    mma_f16(acc[i][j], a[i], &b[j >> 1][(j & 1) * 2]);
        }
    }

    // ---- epilogue: bias + store ----
    const int row0 = by * BM + warp_m * 64;
    const int col0 = bx * BN + warp_n * 64;
    const int lrow = lid >> 2;
    const int lcol = (lid & 3) * 2;
#pragma unroll
    for (int j = 0; j < 8; j++) {
        int c0 = col0 + j * 8 + lcol;
        float2 bv = *reinterpret_cast<const float2*>(bias + c0);
#pragma unroll
        for (int i = 0; i < 4; i++) {
            int r = row0 + i * 16 + lrow;
            float2 o0 = {acc[i][j][0] + bv.x, acc[i][j][1] + bv.y};
            float2 o1 = {acc[i][j][2] + bv.x, acc[i][j][3] + bv.y};
            *reinterpret_cast<float2*>(out + (size_t)r * NDIM + c0) = o0;
            *reinterpret_cast<float2*>(out + (size_t)(r + 8) * NDIM + c0) = o1;
        }
    }
}

// ---------------------------------------------------------------------------
// Launch: prep forked onto two streams, GEMM after join.
// ---------------------------------------------------------------------------
extern "C" void kernel_launch(void* const* d_in, const int* in_sizes, int n_in,
                              void* d_out, int out_size) {
    const float* x      = (const float*)d_in[0];  // [4,2048,1024]
    const float* binary = (const float*)d_in[1];  // [8,1024,1024]
    const float* scale  = (const float*)d_in[2];  // [8,1,1024]
    const float* bias   = (const float*)d_in[3];  // [1024]
    float* out = (float*)d_out;

    static cudaStream_t s2 = nullptr;
    static cudaEvent_t evFork = nullptr, evJoin = nullptr;
    static int init = 0;
    if (!init) {
        cudaStreamCreateWithFlags(&s2, cudaStreamNonBlocking);
        cudaEventCreateWithFlags(&evFork, cudaEventDisableTiming);
        cudaEventCreateWithFlags(&evJoin, cudaEventDisableTiming);
        cudaFuncSetAttribute(gemm_kernel, cudaFuncAttributeMaxDynamicSharedMemorySize, SMEM_DYN);
        init = 1;
    }

    cudaEventRecord(evFork, 0);
    cudaStreamWaitEvent(s2, evFork, 0);
    fold_kernel<<<dim3(NDIM / 128, MDIM / 32), 256, 0, s2>>>(binary, scale);
    split_x_kernel<<<(TROWS * MDIM) / 16 / 256, 256>>>(x);
    cudaEventRecord(evJoin, s2);
    cudaStreamWaitEvent(0, evJoin, 0);

    gemm_kernel<<<dim3(NDIM / BN, TROWS / BM), 128, SMEM_DYN>>>(bias, out);
}